// round 1
// baseline (speedup 1.0000x reference)
#include <cuda_runtime.h>

#define BB 8
#define NN 1024
#define EE 1536
#define FIN 64
#define FOUT 64
#define FE 32
#define MAXDEG 64

// Scratch (device globals — no allocation allowed)
__device__ float g_h[BB * NN * FOUT];      // nodes @ W
__device__ float g_ew[BB * EE];            // edge feature reduction
__device__ int   g_ep0[EE];                // edge endpoint 0
__device__ int   g_ep1[EE];                // edge endpoint 1
__device__ int   g_ecnt[EE];               // endpoint slot counter
__device__ int   g_deg[NN];                // node degree
__device__ int   g_adj[NN * MAXDEG];       // per-node incident edge list

// ---------------------------------------------------------------------------
// K1: role-split kernel.
//   blocks [0,10):        reset g_ecnt / g_deg
//   blocks [10,1546):     ew[b,e] = edges[b,e,:] . evec   (warp per (b,e))
//   blocks [1546,1802):   h = nodes @ W, 32-row tiles, smem-tiled
// ---------------------------------------------------------------------------
__global__ void __launch_bounds__(256) k1_init_ew_gemm(
    const float* __restrict__ nodes,
    const float* __restrict__ edges,
    const float* __restrict__ W,
    const float* __restrict__ evec)
{
    __shared__ float sW[64 * 64];   // 16 KB
    __shared__ float sX[32 * 64];   // 8 KB
    const int bx = blockIdx.x;
    const int tid = threadIdx.x;

    if (bx < 10) {
        int idx = bx * 256 + tid;
        if (idx < EE) g_ecnt[idx] = 0;
        else if (idx < EE + NN) g_deg[idx - EE] = 0;
        return;
    }

    if (bx < 10 + 1536) {
        // warp per (b,e) flattened index
        int be = (bx - 10) * 8 + (tid >> 5);      // in [0, B*E)
        int lane = tid & 31;
        float v = edges[be * FE + lane] * evec[lane];
        #pragma unroll
        for (int o = 16; o; o >>= 1) v += __shfl_xor_sync(0xffffffffu, v, o);
        if (lane == 0) g_ew[be] = v;
        return;
    }

    // h-GEMM: tile of 32 global rows (rows flattened over B*N = 8192)
    const int rb = (bx - 1546) * 32;
    for (int t = tid; t < 64 * 64; t += 256) sW[t] = W[t];
    for (int t = tid; t < 32 * 64; t += 256) sX[t] = nodes[rb * 64 + t];
    __syncthreads();

    const int f  = tid & 63;
    const int rg = tid >> 6;   // 0..3, each handles 8 rows
    float acc[8];
    #pragma unroll
    for (int j = 0; j < 8; j++) acc[j] = 0.f;

    #pragma unroll 8
    for (int k = 0; k < 64; k++) {
        float wv = sW[k * 64 + f];
        #pragma unroll
        for (int j = 0; j < 8; j++)
            acc[j] += sX[(rg * 8 + j) * 64 + k] * wv;
    }
    #pragma unroll
    for (int j = 0; j < 8; j++)
        g_h[(rb + rg * 8 + j) * 64 + f] = acc[j];
}

// ---------------------------------------------------------------------------
// K2: extract graph structure from dense incidence matrix [N, E].
// Coalesced scan; each nonzero records its node into the edge's endpoint
// slots and appends the edge to the node's adjacency list.
// ---------------------------------------------------------------------------
__global__ void __launch_bounds__(256) k2_extract(const float* __restrict__ inc)
{
    int idx = blockIdx.x * 256 + threadIdx.x;  // < N*E = 1572864
    float v = inc[idx];
    if (v != 0.f) {
        int i = idx / EE;
        int e = idx - i * EE;
        int s = atomicAdd(&g_ecnt[e], 1);
        if (s == 0) g_ep0[e] = i; else g_ep1[e] = i;
        int d = atomicAdd(&g_deg[i], 1);
        if (d < MAXDEG) g_adj[i * MAXDEG + d] = e;
    }
}

// ---------------------------------------------------------------------------
// K3: sparse gather. Block per node i; 512 threads = (b in 0..7) x (f in 0..63).
// out[b,i,f] = lap[i,i]*S_i(b)*h[b,i,f] + sum_{e incident i} lap[i,o]*ew[b,e]*h[b,o,f]
// ---------------------------------------------------------------------------
__global__ void __launch_bounds__(512) k3_gather(
    const float* __restrict__ lap, float* __restrict__ out)
{
    __shared__ int   se[MAXDEG];
    __shared__ int   so[MAXDEG];
    __shared__ float sl[MAXDEG];
    __shared__ float s_lapii;

    const int i = blockIdx.x;
    const int tid = threadIdx.x;

    int d = g_deg[i];
    if (d > MAXDEG) d = MAXDEG;

    if (tid < d) {
        int e  = g_adj[i * MAXDEG + tid];
        int a0 = g_ep0[e];
        int a1 = g_ep1[e];
        int o  = (a0 == i) ? a1 : a0;
        se[tid] = e;
        so[tid] = o;
        sl[tid] = lap[i * NN + o];
    }
    if (tid == 0) s_lapii = lap[i * NN + i];
    __syncthreads();

    const int b = tid >> 6;
    const int f = tid & 63;
    const float* hb  = g_h + b * (NN * 64);
    const float* ewb = g_ew + b * EE;

    float hv  = hb[i * 64 + f];
    float acc = 0.f;
    float S   = 0.f;
    for (int j = 0; j < d; j++) {
        float w = ewb[se[j]];        // broadcast within warp
        S += w;
        acc += sl[j] * w * hb[so[j] * 64 + f];  // coalesced 128B per warp
    }
    out[(b * NN + i) * 64 + f] = s_lapii * S * hv + acc;
}

// ---------------------------------------------------------------------------
extern "C" void kernel_launch(void* const* d_in, const int* in_sizes, int n_in,
                              void* d_out, int out_size)
{
    const float* nodes = (const float*)d_in[0];   // [8,1024,64]
    const float* edges = (const float*)d_in[1];   // [8,1536,32]
    const float* W     = (const float*)d_in[2];   // [64,64]
    const float* evec  = (const float*)d_in[3];   // [32]
    const float* inc   = (const float*)d_in[4];   // [1024,1536]
    const float* lap   = (const float*)d_in[5];   // [1024,1024]
    float* out = (float*)d_out;                   // [8,1024,64]

    (void)in_sizes; (void)n_in; (void)out_size;

    k1_init_ew_gemm<<<1802, 256>>>(nodes, edges, W, evec);
    k2_extract<<<6144, 256>>>(inc);
    k3_gather<<<1024, 512>>>(lap, out);
}

// round 4
// speedup vs baseline: 1.3720x; 1.3720x over previous
// v3 — identical algorithm to v2; resubmitted after broker-level container
// failures (no kernel-attributable error evidence).
#include <cuda_runtime.h>

#define BB 8
#define NN 1024
#define EE 1536
#define FIN 64
#define FOUT 64
#define FE 32
#define MAXDEG 64

// Scratch (device globals, zero-initialized at module load).
// g_ecnt/g_deg are reset at the end of k3 each run, so every kernel_launch
// call observes them zeroed (first call: .bss zero-init).
__device__ float g_h[BB * NN * FOUT];      // nodes @ W
__device__ float g_ew[BB * EE];            // edge feature reduction
__device__ int   g_ep0[EE];                // edge endpoint 0
__device__ int   g_ep1[EE];                // edge endpoint 1
__device__ int   g_ecnt[EE];               // endpoint slot counter (zeroed)
__device__ int   g_deg[NN];                // node degree (zeroed)
__device__ int   g_adj[NN * MAXDEG];       // per-node incident edge list

// ---------------------------------------------------------------------------
// K1 fused: one wave of 272 blocks x 256 threads.
//   blocks [0,128):    h = nodes @ W     (64-row tile, 4x4 register blocking)
//   blocks [128,224):  extract graph structure from inc [N,E] (float4 scan)
//   blocks [224,272):  ew[b,e] = edges[b,e,:] . evec  (4 edges per warp-iter)
// ---------------------------------------------------------------------------
#define G_GEMM 128
#define G_EXT  96
#define G_EW   48
#define G_K1   (G_GEMM + G_EXT + G_EW)

__global__ void __launch_bounds__(256) k1_fused(
    const float* __restrict__ nodes,
    const float* __restrict__ edges,
    const float* __restrict__ W,
    const float* __restrict__ evec,
    const float* __restrict__ inc)
{
    __shared__ float sX[64][65];   // padded: conflict-free column reads
    __shared__ float sW[64 * 64];
    const int bx  = blockIdx.x;
    const int tid = threadIdx.x;

    if (bx < G_GEMM) {
        // ----- GEMM role: rows [rb, rb+64) of the flattened [8192,64] X -----
        const int rb = bx * 64;

        for (int t = tid; t < 1024; t += 256)
            ((float4*)sW)[t] = ((const float4*)W)[t];
        for (int t = tid; t < 1024; t += 256) {
            float4 v = ((const float4*)nodes)[rb * 16 + t];
            int r = t >> 4;
            int c = (t & 15) << 2;
            sX[r][c + 0] = v.x; sX[r][c + 1] = v.y;
            sX[r][c + 2] = v.z; sX[r][c + 3] = v.w;
        }
        __syncthreads();

        const int cg = tid & 15;    // 4 output cols: 4*cg..
        const int rg = tid >> 4;    // 4 output rows: 4*rg..
        float acc[4][4];
        #pragma unroll
        for (int r = 0; r < 4; r++)
            #pragma unroll
            for (int c = 0; c < 4; c++) acc[r][c] = 0.f;

        #pragma unroll 8
        for (int k = 0; k < 64; k++) {
            float4 wv = *(const float4*)&sW[k * 64 + cg * 4];
            float x0 = sX[rg * 4 + 0][k];
            float x1 = sX[rg * 4 + 1][k];
            float x2 = sX[rg * 4 + 2][k];
            float x3 = sX[rg * 4 + 3][k];
            acc[0][0] += x0 * wv.x; acc[0][1] += x0 * wv.y;
            acc[0][2] += x0 * wv.z; acc[0][3] += x0 * wv.w;
            acc[1][0] += x1 * wv.x; acc[1][1] += x1 * wv.y;
            acc[1][2] += x1 * wv.z; acc[1][3] += x1 * wv.w;
            acc[2][0] += x2 * wv.x; acc[2][1] += x2 * wv.y;
            acc[2][2] += x2 * wv.z; acc[2][3] += x2 * wv.w;
            acc[3][0] += x3 * wv.x; acc[3][1] += x3 * wv.y;
            acc[3][2] += x3 * wv.z; acc[3][3] += x3 * wv.w;
        }

        #pragma unroll
        for (int r = 0; r < 4; r++) {
            float4 st = make_float4(acc[r][0], acc[r][1], acc[r][2], acc[r][3]);
            ((float4*)g_h)[(rb + rg * 4 + r) * 16 + cg] = st;
        }
        return;
    }

    if (bx < G_GEMM + G_EXT) {
        // ----- extract role: coalesced float4 scan of inc [1024,1536] -----
        const int t = (bx - G_GEMM) * 256 + tid;           // 0..24575
        const float4* inc4 = (const float4*)inc;
        #pragma unroll 4
        for (int j = 0; j < 16; j++) {
            int idx4 = j * 24576 + t;                      // < 393216
            float4 v = inc4[idx4];
            int base = idx4 << 2;
            float vals[4] = {v.x, v.y, v.z, v.w};
            #pragma unroll
            for (int c = 0; c < 4; c++) {
                if (vals[c] != 0.f) {
                    int idx = base + c;
                    int i = idx / EE;
                    int e = idx - i * EE;
                    int s = atomicAdd(&g_ecnt[e], 1);
                    if (s == 0) g_ep0[e] = i; else g_ep1[e] = i;
                    int d = atomicAdd(&g_deg[i], 1);
                    if (d < MAXDEG) g_adj[i * MAXDEG + d] = e;
                }
            }
        }
        return;
    }

    // ----- ew role: 4 edges per warp-iter, 8 lanes per edge, float4 loads -----
    {
        const int wb   = (bx - (G_GEMM + G_EXT)) * 8 + (tid >> 5);  // 0..383
        const int lane = tid & 31;
        const int sub  = lane >> 3;          // edge within quad
        const int off  = lane & 7;           // float4 slice of FE=32
        float4 ev = ((const float4*)evec)[off];
        #pragma unroll
        for (int it = 0; it < 8; it++) {
            int e = wb * 32 + it * 4 + sub;  // be index in [0, 12288)
            float4 d = ((const float4*)edges)[e * 8 + off];
            float s = d.x * ev.x + d.y * ev.y + d.z * ev.z + d.w * ev.w;
            s += __shfl_xor_sync(0xffffffffu, s, 4);
            s += __shfl_xor_sync(0xffffffffu, s, 2);
            s += __shfl_xor_sync(0xffffffffu, s, 1);
            if (off == 0) g_ew[e] = s;
        }
    }
}

// ---------------------------------------------------------------------------
// K3: sparse gather. Block per node i; 512 threads = (b in 0..7) x (f in 0..63).
// out[b,i,f] = lap[i,i]*S_i(b)*h[b,i,f] + sum_{e inc. i} lap[i,o]*ew[b,e]*h[b,o,f]
// Also resets g_deg / g_ecnt for the next run.
// ---------------------------------------------------------------------------
__global__ void __launch_bounds__(512) k3_gather(
    const float* __restrict__ lap, float* __restrict__ out)
{
    __shared__ int   se[MAXDEG];
    __shared__ int   so[MAXDEG];
    __shared__ float sl[MAXDEG];
    __shared__ float s_lapii;

    const int i = blockIdx.x;
    const int tid = threadIdx.x;

    int d = g_deg[i];                 // read by ALL threads before the barrier
    if (d > MAXDEG) d = MAXDEG;

    if (tid < d) {
        int e  = g_adj[i * MAXDEG + tid];
        int a0 = g_ep0[e];
        int a1 = g_ep1[e];
        int o  = (a0 == i) ? a1 : a0;
        se[tid] = e;
        so[tid] = o;
        sl[tid] = lap[i * NN + o];
    }
    if (tid == 0) s_lapii = lap[i * NN + i];
    __syncthreads();

    // reset state for the next launch (no thread reads these again)
    if (tid == 0) g_deg[i] = 0;
    if (i < 512 && tid >= 1 && tid <= 3) g_ecnt[i + (tid - 1) * 512] = 0;

    const int b = tid >> 6;
    const int f = tid & 63;
    const float* hb  = g_h + b * (NN * 64);
    const float* ewb = g_ew + b * EE;

    float hv  = hb[i * 64 + f];
    float acc = 0.f;
    float S   = 0.f;
    for (int j = 0; j < d; j++) {
        float w = ewb[se[j]];                      // warp broadcast
        S += w;
        acc += sl[j] * w * hb[so[j] * 64 + f];     // coalesced 256B per warp-pair
    }
    out[(b * NN + i) * 64 + f] = s_lapii * S * hv + acc;
}

// ---------------------------------------------------------------------------
extern "C" void kernel_launch(void* const* d_in, const int* in_sizes, int n_in,
                              void* d_out, int out_size)
{
    const float* nodes = (const float*)d_in[0];   // [8,1024,64]
    const float* edges = (const float*)d_in[1];   // [8,1536,32]
    const float* W     = (const float*)d_in[2];   // [64,64]
    const float* evec  = (const float*)d_in[3];   // [32]
    const float* inc   = (const float*)d_in[4];   // [1024,1536]
    const float* lap   = (const float*)d_in[5];   // [1024,1024]
    float* out = (float*)d_out;                   // [8,1024,64]

    (void)in_sizes; (void)n_in; (void)out_size;

    k1_fused<<<G_K1, 256>>>(nodes, edges, W, evec, inc);
    k3_gather<<<1024, 512>>>(lap, out);
}

// round 5
// speedup vs baseline: 1.4984x; 1.0921x over previous
// v4 — k3: 2 nodes/block (one-wave grid, 2x gather MLP); k1: finer role grids.
#include <cuda_runtime.h>

#define BB 8
#define NN 1024
#define EE 1536
#define FE 32
#define MAXDEG 64

__device__ float g_h[BB * NN * 64];
__device__ float g_ew[BB * EE];
__device__ int   g_ep0[EE];
__device__ int   g_ep1[EE];
__device__ int   g_ecnt[EE];   // zeroed at load; re-zeroed by k3
__device__ int   g_deg[NN];    // zeroed at load; re-zeroed by k3
__device__ int   g_adj[NN * MAXDEG];

// ---------------------------------------------------------------------------
// K1 fused: 496 blocks x 256 threads, one wave (~3.4 CTA/SM).
//   [0,256):    h = nodes @ W   (32-row tile, 2x4 register micro-tile)
//   [256,448):  extract graph from inc [N,E] (float4 scan, 8 iters)
//   [448,496):  ew[b,e] = edges[b,e,:] . evec
// ---------------------------------------------------------------------------
#define G_GEMM 256
#define G_EXT  192
#define G_EW   48
#define G_K1   (G_GEMM + G_EXT + G_EW)

__global__ void __launch_bounds__(256) k1_fused(
    const float* __restrict__ nodes,
    const float* __restrict__ edges,
    const float* __restrict__ W,
    const float* __restrict__ evec,
    const float* __restrict__ inc)
{
    __shared__ float sX[32][65];
    __shared__ float sW[64 * 64];
    const int bx  = blockIdx.x;
    const int tid = threadIdx.x;

    if (bx < G_GEMM) {
        const int rb = bx * 32;                     // rows [rb, rb+32)
        for (int t = tid; t < 1024; t += 256)
            ((float4*)sW)[t] = ((const float4*)W)[t];
        for (int t = tid; t < 512; t += 256) {
            float4 v = ((const float4*)nodes)[rb * 16 + t];
            int r = t >> 4, c = (t & 15) << 2;
            sX[r][c + 0] = v.x; sX[r][c + 1] = v.y;
            sX[r][c + 2] = v.z; sX[r][c + 3] = v.w;
        }
        __syncthreads();

        const int cg = tid & 15;                    // cols 4cg..4cg+3
        const int rg = tid >> 4;                    // rows 2rg, 2rg+1
        float a0x=0,a0y=0,a0z=0,a0w=0, a1x=0,a1y=0,a1z=0,a1w=0;

        #pragma unroll 8
        for (int k = 0; k < 64; k++) {
            float4 wv = *(const float4*)&sW[k * 64 + cg * 4];
            float x0 = sX[rg * 2 + 0][k];
            float x1 = sX[rg * 2 + 1][k];
            a0x += x0 * wv.x; a0y += x0 * wv.y; a0z += x0 * wv.z; a0w += x0 * wv.w;
            a1x += x1 * wv.x; a1y += x1 * wv.y; a1z += x1 * wv.z; a1w += x1 * wv.w;
        }
        ((float4*)g_h)[(rb + rg * 2 + 0) * 16 + cg] = make_float4(a0x, a0y, a0z, a0w);
        ((float4*)g_h)[(rb + rg * 2 + 1) * 16 + cg] = make_float4(a1x, a1y, a1z, a1w);
        return;
    }

    if (bx < G_GEMM + G_EXT) {
        const int t = (bx - G_GEMM) * 256 + tid;    // 0..49151
        const float4* inc4 = (const float4*)inc;
        #pragma unroll 4
        for (int j = 0; j < 8; j++) {
            int idx4 = j * 49152 + t;               // < 393216
            float4 v = inc4[idx4];
            int base = idx4 << 2;
            float vals[4] = {v.x, v.y, v.z, v.w};
            #pragma unroll
            for (int c = 0; c < 4; c++) {
                if (vals[c] != 0.f) {
                    int idx = base + c;
                    int i = idx / EE;
                    int e = idx - i * EE;
                    int s = atomicAdd(&g_ecnt[e], 1);
                    if (s == 0) g_ep0[e] = i; else g_ep1[e] = i;
                    int d = atomicAdd(&g_deg[i], 1);
                    if (d < MAXDEG) g_adj[i * MAXDEG + d] = e;
                }
            }
        }
        return;
    }

    {   // ew role
        const int wb   = (bx - (G_GEMM + G_EXT)) * 8 + (tid >> 5);  // 0..383
        const int lane = tid & 31;
        const int sub  = lane >> 3;
        const int off  = lane & 7;
        float4 ev = ((const float4*)evec)[off];
        #pragma unroll
        for (int it = 0; it < 8; it++) {
            int e = wb * 32 + it * 4 + sub;         // < 12288
            float4 d = ((const float4*)edges)[e * 8 + off];
            float s = d.x * ev.x + d.y * ev.y + d.z * ev.z + d.w * ev.w;
            s += __shfl_xor_sync(0xffffffffu, s, 4);
            s += __shfl_xor_sync(0xffffffffu, s, 2);
            s += __shfl_xor_sync(0xffffffffu, s, 1);
            if (off == 0) g_ew[e] = s;
        }
    }
}

// ---------------------------------------------------------------------------
// K3: sparse gather, 2 nodes per block -> 512 blocks = ONE wave (4 CTA/SM).
// 512 threads = (b 0..7) x (f 0..63). Both nodes' gather loops are
// independent -> 2x memory-level parallelism per thread.
// Also resets g_deg / g_ecnt for the next run.
// ---------------------------------------------------------------------------
__global__ void __launch_bounds__(512) k3_gather(
    const float* __restrict__ lap, float* __restrict__ out)
{
    __shared__ int   se[2][MAXDEG];
    __shared__ int   so[2][MAXDEG];
    __shared__ float sl[2][MAXDEG];
    __shared__ int   sdeg[2];
    __shared__ float slii[2];

    const int i0  = blockIdx.x * 2;
    const int tid = threadIdx.x;

    if (tid < 128) {
        const int g    = tid >> 6;
        const int slot = tid & 63;
        const int i    = i0 + g;
        int d = g_deg[i];
        if (d > MAXDEG) d = MAXDEG;
        if (slot == 0) { sdeg[g] = d; slii[g] = lap[i * NN + i]; }
        if (slot < d) {
            int e  = g_adj[i * MAXDEG + slot];
            int a0 = g_ep0[e];
            int a1 = g_ep1[e];
            int o  = (a0 == i) ? a1 : a0;
            se[g][slot] = e;
            so[g][slot] = o;
            sl[g][slot] = lap[i * NN + o];
        }
    }
    __syncthreads();

    // reset persistent state (nothing below reads these)
    if (tid == 0) { g_deg[i0] = 0; g_deg[i0 + 1] = 0; }
    if (tid >= 1 && tid <= 3) g_ecnt[blockIdx.x + (tid - 1) * 512] = 0;

    const int b = tid >> 6;
    const int f = tid & 63;
    const float* hb  = g_h + b * (NN * 64);
    const float* ewb = g_ew + b * EE;

    const int   d0 = sdeg[0], d1 = sdeg[1];
    float hv0 = hb[(i0 + 0) * 64 + f];
    float hv1 = hb[(i0 + 1) * 64 + f];

    float S0 = 0.f, acc0 = 0.f;
    for (int j = 0; j < d0; j++) {
        float w = ewb[se[0][j]];
        S0   += w;
        acc0 += sl[0][j] * w * hb[so[0][j] * 64 + f];
    }
    float S1 = 0.f, acc1 = 0.f;
    for (int j = 0; j < d1; j++) {
        float w = ewb[se[1][j]];
        S1   += w;
        acc1 += sl[1][j] * w * hb[so[1][j] * 64 + f];
    }

    out[(b * NN + i0 + 0) * 64 + f] = slii[0] * S0 * hv0 + acc0;
    out[(b * NN + i0 + 1) * 64 + f] = slii[1] * S1 * hv1 + acc1;
}

// ---------------------------------------------------------------------------
extern "C" void kernel_launch(void* const* d_in, const int* in_sizes, int n_in,
                              void* d_out, int out_size)
{
    const float* nodes = (const float*)d_in[0];   // [8,1024,64]
    const float* edges = (const float*)d_in[1];   // [8,1536,32]
    const float* W     = (const float*)d_in[2];   // [64,64]
    const float* evec  = (const float*)d_in[3];   // [32]
    const float* inc   = (const float*)d_in[4];   // [1024,1536]
    const float* lap   = (const float*)d_in[5];   // [1024,1024]
    float* out = (float*)d_out;                   // [8,1024,64]

    (void)in_sizes; (void)n_in; (void)out_size;

    k1_fused<<<G_K1, 256>>>(nodes, edges, W, evec, inc);
    k3_gather<<<512, 512>>>(lap, out);
}